// round 2
// baseline (speedup 1.0000x reference)
#include <cuda_runtime.h>

#define D_IN 128
#define HC 256          // HEADS * C_OUT
#define N_NODES_MAX 50000
#define E_MAX 800000

// Scratch (allocation-free rule: __device__ globals)
__device__ float g_XL[(size_t)N_NODES_MAX * HC];   // x @ W_l, [N,256]
__device__ float g_XR[(size_t)N_NODES_MAX * HC];   // x @ W_r, [N,256]
__device__ int   g_deg [N_NODES_MAX];
__device__ int   g_offs[N_NODES_MAX + 1];
__device__ int   g_cur [N_NODES_MAX];
__device__ int   g_esrc[E_MAX];                    // CSR: sources grouped by dst

// ---------------------------------------------------------------------------
// Fused dual-output GEMM:  XL = x @ W_l,  XR = x @ W_r
// M=50000, K=128, 256 cols each. 64x64 tiles, BK=16, 256 threads, 4x4 micro.
// ---------------------------------------------------------------------------
__global__ void __launch_bounds__(256) gemm_kernel(
    const float* __restrict__ x,
    const float* __restrict__ Wl,
    const float* __restrict__ Wr,
    int M)
{
    __shared__ __align__(16) float As[64][17];
    __shared__ __align__(16) float Bs[16][64];

    int by = blockIdx.y;                  // 0..7 : col tile over [W_l | W_r]
    const float* W = (by < 4) ? Wl : Wr;
    float*       C = (by < 4) ? g_XL : g_XR;
    int colbase = (by & 3) * 64;
    int row0 = blockIdx.x * 64;

    int tid = threadIdx.x;
    int tx = tid & 15, ty = tid >> 4;

    // loader indices
    int ar = tid >> 2, ak = (tid & 3) * 4;     // A: row 0..63, 4 k's (float4)
    int br = tid >> 4, bc = (tid & 15) * 4;    // B: k-row 0..15, 4 cols

    float acc[4][4] = {};

    for (int k0 = 0; k0 < D_IN; k0 += 16) {
        int grow = row0 + ar;
        float4 av = make_float4(0.f, 0.f, 0.f, 0.f);
        if (grow < M)
            av = *(const float4*)(x + (size_t)grow * D_IN + k0 + ak);
        As[ar][ak + 0] = av.x; As[ar][ak + 1] = av.y;
        As[ar][ak + 2] = av.z; As[ar][ak + 3] = av.w;

        float4 bv = *(const float4*)(W + (size_t)(k0 + br) * HC + colbase + bc);
        *(float4*)&Bs[br][bc] = bv;
        __syncthreads();

#pragma unroll
        for (int k = 0; k < 16; k++) {
            float a[4];
#pragma unroll
            for (int i = 0; i < 4; i++) a[i] = As[ty * 4 + i][k];
            float4 b4 = *(const float4*)&Bs[k][tx * 4];
            float b[4] = {b4.x, b4.y, b4.z, b4.w};
#pragma unroll
            for (int i = 0; i < 4; i++)
#pragma unroll
                for (int j = 0; j < 4; j++) acc[i][j] += a[i] * b[j];
        }
        __syncthreads();
    }

#pragma unroll
    for (int i = 0; i < 4; i++) {
        int grow = row0 + ty * 4 + i;
        if (grow < M) {
            float4 v = make_float4(acc[i][0], acc[i][1], acc[i][2], acc[i][3]);
            *(float4*)(C + (size_t)grow * HC + colbase + tx * 4) = v;
        }
    }
}

// ---------------------------------------------------------------------------
// CSR build
// ---------------------------------------------------------------------------
__global__ void init_kernel(int n) {
    int i = blockIdx.x * blockDim.x + threadIdx.x;
    if (i < n) { g_deg[i] = 0; g_cur[i] = 0; }
}

__global__ void count_kernel(const int* __restrict__ dst, int E) {
    int i = blockIdx.x * blockDim.x + threadIdx.x;
    if (i < E) atomicAdd(&g_deg[dst[i]], 1);
}

// single-block exclusive scan over 50001 offsets
__global__ void scan_kernel(int n) {
    __shared__ int s[1024];
    __shared__ int carry_s;
    if (threadIdx.x == 0) { carry_s = 0; g_offs[0] = 0; }
    __syncthreads();
    for (int base = 0; base < n; base += 1024) {
        int idx = base + threadIdx.x;
        int v = (idx < n) ? g_deg[idx] : 0;
        s[threadIdx.x] = v;
        __syncthreads();
        for (int off = 1; off < 1024; off <<= 1) {
            int t = (threadIdx.x >= off) ? s[threadIdx.x - off] : 0;
            __syncthreads();
            s[threadIdx.x] += t;
            __syncthreads();
        }
        if (idx < n) g_offs[idx + 1] = carry_s + s[threadIdx.x];
        __syncthreads();
        if (threadIdx.x == 0) carry_s += s[1023];
        __syncthreads();
    }
}

__global__ void scatter_kernel(const int* __restrict__ src,
                               const int* __restrict__ dst, int E) {
    int i = blockIdx.x * blockDim.x + threadIdx.x;
    if (i < E) {
        int d = dst[i];
        int pos = g_offs[d] + atomicAdd(&g_cur[d], 1);
        g_esrc[pos] = src[i];
    }
}

// ---------------------------------------------------------------------------
// Single-pass GATv2 aggregation.
// Block per dst node (128 thr = 4 warps, warp h owns head h, lane owns 2 ch).
// Online softmax without max-shift (|e| std ~1, exp is safe in fp32):
//   acc  += exp(e) * XL[src],  den += exp(e);  out = mean_h(acc/den) + bias
// Self-loop appended as the (end) iteration.
// ---------------------------------------------------------------------------
__global__ void __launch_bounds__(128) agg_kernel(
    const float* __restrict__ att,
    const float* __restrict__ bias,
    float* __restrict__ out, int N)
{
    int i = blockIdx.x;
    int tid = threadIdx.x;
    int h = tid >> 5;
    int lane = tid & 31;
    int cbase = h * 64 + lane * 2;

    float2 xr2 = *(const float2*)(g_XR + (size_t)i * HC + cbase);
    float2 at2 = *(const float2*)(att + cbase);

    float acc0 = 0.f, acc1 = 0.f, den = 0.f;
    int beg = g_offs[i], end = g_offs[i + 1];

    for (int e = beg; e <= end; e++) {
        int src = (e < end) ? g_esrc[e] : i;   // e==end -> self loop
        float2 xl2 = *(const float2*)(g_XL + (size_t)src * HC + cbase);
        float m0 = xl2.x + xr2.x;
        float m1 = xl2.y + xr2.y;
        m0 = (m0 > 0.f) ? m0 : 0.2f * m0;
        m1 = (m1 > 0.f) ? m1 : 0.2f * m1;
        float d = m0 * at2.x + m1 * at2.y;
#pragma unroll
        for (int off = 16; off; off >>= 1)
            d += __shfl_xor_sync(0xffffffffu, d, off);
        float w = __expf(d);
        acc0 += w * xl2.x;
        acc1 += w * xl2.y;
        den  += w;
    }

    __shared__ float s[4][64];
    float inv = 1.f / den;
    s[h][lane * 2 + 0] = acc0 * inv;
    s[h][lane * 2 + 1] = acc1 * inv;
    __syncthreads();

    if (tid < 64) {
        float v = 0.25f * (s[0][tid] + s[1][tid] + s[2][tid] + s[3][tid]) + bias[tid];
        out[(size_t)i * 64 + tid] = v;
    }
}

// ---------------------------------------------------------------------------
extern "C" void kernel_launch(void* const* d_in, const int* in_sizes, int n_in,
                              void* d_out, int out_size)
{
    const float* x    = (const float*)d_in[0];
    const int*   ei   = (const int*)d_in[1];
    const float* Wl   = (const float*)d_in[2];
    const float* Wr   = (const float*)d_in[3];
    const float* att  = (const float*)d_in[4];
    const float* bias = (const float*)d_in[5];
    float*       out  = (float*)d_out;

    int N = in_sizes[0] / D_IN;
    int E = in_sizes[1] / 2;
    const int* src = ei;
    const int* dst = ei + E;

    init_kernel<<<(N + 255) / 256, 256>>>(N);

    dim3 ggrid((N + 63) / 64, 8);
    gemm_kernel<<<ggrid, 256>>>(x, Wl, Wr, N);

    count_kernel<<<(E + 255) / 256, 256>>>(dst, E);
    scan_kernel<<<1, 1024>>>(N);
    scatter_kernel<<<(E + 255) / 256, 256>>>(src, dst, E);

    agg_kernel<<<N, 128>>>(att, bias, out, N);
}

// round 4
// speedup vs baseline: 1.1856x; 1.1856x over previous
#include <cuda_runtime.h>

#define D_IN 128
#define HC 256          // HEADS * C_OUT
#define N_NODES_MAX 50000
#define E_MAX 800000

#define BM 128
#define BN 64
#define BK 16

// Scratch (allocation-free rule: __device__ globals)
__device__ float g_XL[(size_t)N_NODES_MAX * HC];   // x @ W_l, [N,256]
__device__ float g_XR[(size_t)N_NODES_MAX * HC];   // x @ W_r, [N,256]
__device__ int   g_deg [N_NODES_MAX];
__device__ int   g_offs[N_NODES_MAX + 1];
__device__ int   g_cur [N_NODES_MAX];
__device__ int   g_esrc[E_MAX];                    // CSR: sources grouped by dst
__device__ int   g_scan[N_NODES_MAX];              // block-inclusive scans
__device__ int   g_bsum[64];
__device__ int   g_bpre[64];

// ---------------------------------------------------------------------------
// Fused dual-output GEMM:  XL = x @ W_l,  XR = x @ W_r
// 128x64 tiles, BK=16, 256 threads, 8x4 micro-tile, k-major As (transposed
// store), double-buffered smem.
// ---------------------------------------------------------------------------
__global__ void __launch_bounds__(256) gemm_kernel(
    const float* __restrict__ x,
    const float* __restrict__ Wl,
    const float* __restrict__ Wr,
    int M)
{
    __shared__ __align__(16) float As[2][BK][BM];   // k-major: As[k][row]
    __shared__ __align__(16) float Bs[2][BK][BN];   // Bs[k][col]

    int by = blockIdx.y;                  // 0..7 : col tile over [W_l | W_r]
    const float* W = (by < 4) ? Wl : Wr;
    float*       C = (by < 4) ? g_XL : g_XR;
    int colbase = (by & 3) * BN;
    int row0 = blockIdx.x * BM;

    int tid = threadIdx.x;
    int tx = tid & 15, ty = tid >> 4;     // tx: col group (4 cols), ty: row group (8 rows)

    // A loader: row = tid & 127, kgroup = tid >> 7 (covers k a_kg0..+3 and a_kg0+8..+11)
    int a_row  = tid & 127;
    int a_kg0  = (tid >> 7) * 4;
    // B loader: k-row = tid >> 4 (0..15), col = (tid & 15) * 4
    int b_k = tid >> 4, b_c = (tid & 15) * 4;

    float acc[8][4] = {};
    float4 a_pre0, a_pre1, b_pre;

    // ---- prefetch k-tile 0 into registers ----
    {
        int grow = row0 + a_row;
        a_pre0 = a_pre1 = make_float4(0.f, 0.f, 0.f, 0.f);
        if (grow < M) {
            a_pre0 = *(const float4*)(x + (size_t)grow * D_IN + a_kg0);
            a_pre1 = *(const float4*)(x + (size_t)grow * D_IN + a_kg0 + 8);
        }
        b_pre = *(const float4*)(W + (size_t)b_k * HC + colbase + b_c);
    }
    // store stage 0
    {
        As[0][a_kg0 + 0][a_row] = a_pre0.x; As[0][a_kg0 + 1][a_row] = a_pre0.y;
        As[0][a_kg0 + 2][a_row] = a_pre0.z; As[0][a_kg0 + 3][a_row] = a_pre0.w;
        As[0][a_kg0 + 8][a_row] = a_pre1.x; As[0][a_kg0 + 9][a_row] = a_pre1.y;
        As[0][a_kg0 +10][a_row] = a_pre1.z; As[0][a_kg0 +11][a_row] = a_pre1.w;
        *(float4*)&Bs[0][b_k][b_c] = b_pre;
    }
    __syncthreads();

    const int NT = D_IN / BK;   // 8 k-tiles
#pragma unroll 1
    for (int kt = 0; kt < NT; kt++) {
        int cur = kt & 1, nxt = cur ^ 1;

        // prefetch next tile to registers (overlaps with compute)
        if (kt + 1 < NT) {
            int k0 = (kt + 1) * BK;
            int grow = row0 + a_row;
            a_pre0 = a_pre1 = make_float4(0.f, 0.f, 0.f, 0.f);
            if (grow < M) {
                a_pre0 = *(const float4*)(x + (size_t)grow * D_IN + k0 + a_kg0);
                a_pre1 = *(const float4*)(x + (size_t)grow * D_IN + k0 + a_kg0 + 8);
            }
            b_pre = *(const float4*)(W + (size_t)(k0 + b_k) * HC + colbase + b_c);
        }

#pragma unroll
        for (int k = 0; k < BK; k++) {
            float4 a0 = *(const float4*)&As[cur][k][ty * 8];
            float4 a1 = *(const float4*)&As[cur][k][ty * 8 + 4];
            float4 b4 = *(const float4*)&Bs[cur][k][tx * 4];
            float a[8] = {a0.x, a0.y, a0.z, a0.w, a1.x, a1.y, a1.z, a1.w};
            float b[4] = {b4.x, b4.y, b4.z, b4.w};
#pragma unroll
            for (int i = 0; i < 8; i++)
#pragma unroll
                for (int j = 0; j < 4; j++) acc[i][j] += a[i] * b[j];
        }

        if (kt + 1 < NT) {
            As[nxt][a_kg0 + 0][a_row] = a_pre0.x; As[nxt][a_kg0 + 1][a_row] = a_pre0.y;
            As[nxt][a_kg0 + 2][a_row] = a_pre0.z; As[nxt][a_kg0 + 3][a_row] = a_pre0.w;
            As[nxt][a_kg0 + 8][a_row] = a_pre1.x; As[nxt][a_kg0 + 9][a_row] = a_pre1.y;
            As[nxt][a_kg0 +10][a_row] = a_pre1.z; As[nxt][a_kg0 +11][a_row] = a_pre1.w;
            *(float4*)&Bs[nxt][b_k][b_c] = b_pre;
            __syncthreads();
        }
    }

#pragma unroll
    for (int i = 0; i < 8; i++) {
        int grow = row0 + ty * 8 + i;
        if (grow < M) {
            float4 v = make_float4(acc[i][0], acc[i][1], acc[i][2], acc[i][3]);
            *(float4*)(C + (size_t)grow * HC + colbase + tx * 4) = v;
        }
    }
}

// ---------------------------------------------------------------------------
// CSR build
// ---------------------------------------------------------------------------
__global__ void init_kernel(int n) {
    int i = blockIdx.x * blockDim.x + threadIdx.x;
    if (i < n) { g_deg[i] = 0; g_cur[i] = 0; }
}

__global__ void count_kernel(const int* __restrict__ dst, int E) {
    int i = blockIdx.x * blockDim.x + threadIdx.x;
    if (i < E) atomicAdd(&g_deg[dst[i]], 1);
}

// Phase 1: per-block inclusive scan of deg (1024/block), emit block sums.
__global__ void __launch_bounds__(1024) scan1_kernel(int n) {
    __shared__ int s[1024];
    int idx = blockIdx.x * 1024 + threadIdx.x;
    int v = (idx < n) ? g_deg[idx] : 0;
    s[threadIdx.x] = v;
    __syncthreads();
#pragma unroll
    for (int off = 1; off < 1024; off <<= 1) {
        int t = (threadIdx.x >= off) ? s[threadIdx.x - off] : 0;
        __syncthreads();
        s[threadIdx.x] += t;
        __syncthreads();
    }
    if (idx < n) g_scan[idx] = s[threadIdx.x];
    if (threadIdx.x == 1023) g_bsum[blockIdx.x] = s[1023];
}

// Phase 2: exclusive scan of block sums (nb <= 64) — shared-memory
// Hillis-Steele over 64 slots (FIX: previous warp-shuffle version broke at
// nb > 32 -> non-monotone offsets -> den=0 -> NaN).
__global__ void __launch_bounds__(64) scan2_kernel(int nb) {
    __shared__ int s[64];
    int t = threadIdx.x;
    int v0 = (t < nb) ? g_bsum[t] : 0;
    s[t] = v0;
    __syncthreads();
#pragma unroll
    for (int off = 1; off < 64; off <<= 1) {
        int u = (t >= off) ? s[t - off] : 0;
        __syncthreads();
        s[t] += u;
        __syncthreads();
    }
    if (t < nb) g_bpre[t] = s[t] - v0;    // inclusive -> exclusive
}

// Phase 3: add block prefixes, write exclusive offsets.
__global__ void scan3_kernel(int n) {
    int idx = blockIdx.x * 1024 + threadIdx.x;
    if (idx < n) g_offs[idx + 1] = g_scan[idx] + g_bpre[blockIdx.x];
    if (idx == 0) g_offs[0] = 0;
}

__global__ void scatter_kernel(const int* __restrict__ src,
                               const int* __restrict__ dst, int E) {
    int i = blockIdx.x * blockDim.x + threadIdx.x;
    if (i < E) {
        int d = dst[i];
        int pos = g_offs[d] + atomicAdd(&g_cur[d], 1);
        g_esrc[pos] = src[i];
    }
}

// ---------------------------------------------------------------------------
// Single-pass GATv2 aggregation.
// Block per dst node (128 thr = 4 warps, warp h owns head h, lane owns 2 ch).
// Online softmax without max-shift (|e| std ~1, exp safe in fp32):
//   acc  += exp(e) * XL[src],  den += exp(e);  out = mean_h(acc/den) + bias
// Self-loop appended as the (end) iteration.
// ---------------------------------------------------------------------------
__global__ void __launch_bounds__(128) agg_kernel(
    const float* __restrict__ att,
    const float* __restrict__ bias,
    float* __restrict__ out, int N)
{
    int i = blockIdx.x;
    int tid = threadIdx.x;
    int h = tid >> 5;
    int lane = tid & 31;
    int cbase = h * 64 + lane * 2;

    float2 xr2 = *(const float2*)(g_XR + (size_t)i * HC + cbase);
    float2 at2 = *(const float2*)(att + cbase);

    float acc0 = 0.f, acc1 = 0.f, den = 0.f;
    int beg = g_offs[i], end = g_offs[i + 1];

    for (int e = beg; e <= end; e++) {
        int src = (e < end) ? g_esrc[e] : i;   // e==end -> self loop
        float2 xl2 = *(const float2*)(g_XL + (size_t)src * HC + cbase);
        float m0 = xl2.x + xr2.x;
        float m1 = xl2.y + xr2.y;
        m0 = (m0 > 0.f) ? m0 : 0.2f * m0;
        m1 = (m1 > 0.f) ? m1 : 0.2f * m1;
        float d = m0 * at2.x + m1 * at2.y;
#pragma unroll
        for (int off = 16; off; off >>= 1)
            d += __shfl_xor_sync(0xffffffffu, d, off);
        float w = __expf(d);
        acc0 += w * xl2.x;
        acc1 += w * xl2.y;
        den  += w;
    }

    __shared__ float s[4][64];
    float inv = 1.f / den;
    s[h][lane * 2 + 0] = acc0 * inv;
    s[h][lane * 2 + 1] = acc1 * inv;
    __syncthreads();

    if (tid < 64) {
        float v = 0.25f * (s[0][tid] + s[1][tid] + s[2][tid] + s[3][tid]) + bias[tid];
        out[(size_t)i * 64 + tid] = v;
    }
}

// ---------------------------------------------------------------------------
extern "C" void kernel_launch(void* const* d_in, const int* in_sizes, int n_in,
                              void* d_out, int out_size)
{
    const float* x    = (const float*)d_in[0];
    const int*   ei   = (const int*)d_in[1];
    const float* Wl   = (const float*)d_in[2];
    const float* Wr   = (const float*)d_in[3];
    const float* att  = (const float*)d_in[4];
    const float* bias = (const float*)d_in[5];
    float*       out  = (float*)d_out;

    int N = in_sizes[0] / D_IN;
    int E = in_sizes[1] / 2;
    const int* src = ei;
    const int* dst = ei + E;

    init_kernel<<<(N + 255) / 256, 256>>>(N);

    dim3 ggrid((N + BM - 1) / BM, 8);
    gemm_kernel<<<ggrid, 256>>>(x, Wl, Wr, N);

    count_kernel<<<(E + 255) / 256, 256>>>(dst, E);

    int nb = (N + 1023) / 1024;
    scan1_kernel<<<nb, 1024>>>(N);
    scan2_kernel<<<1, 64>>>(nb);
    scan3_kernel<<<nb, 1024>>>(N);

    scatter_kernel<<<(E + 255) / 256, 256>>>(src, dst, E);

    agg_kernel<<<N, 128>>>(att, bias, out, N);
}

// round 5
// speedup vs baseline: 1.2639x; 1.0661x over previous
#include <cuda_runtime.h>

#define D_IN 128
#define HC 256          // HEADS * C_OUT
#define N_NODES_MAX 50000
#define E_MAX 800000

#define BM 128
#define BN 128
#define BK 16

// Scratch (allocation-free rule: __device__ globals)
__device__ float g_XL[(size_t)N_NODES_MAX * HC];   // x @ W_l, [N,256]
__device__ float g_XR[(size_t)N_NODES_MAX * HC];   // x @ W_r, [N,256]
__device__ int   g_deg [N_NODES_MAX];
__device__ int   g_offs[N_NODES_MAX + 1];
__device__ int   g_cur [N_NODES_MAX];
__device__ int   g_esrc[E_MAX];                    // CSR: sources grouped by dst
__device__ int   g_scan[N_NODES_MAX];              // block-inclusive scans
__device__ int   g_bsum[64];
__device__ int   g_bpre[64];

// ---------------------------------------------------------------------------
// Fused dual-output GEMM:  XL = x @ W_l,  XR = x @ W_r
// 128x128 tiles, BK=16, 256 threads, 8x8 micro-tile (1.0 B smem / FFMA),
// k-major As (transposed store), double-buffered smem.
// b columns split as [tx*4, tx*4+64] for conflict-free 16B-stride LDS.
// ---------------------------------------------------------------------------
__global__ void __launch_bounds__(256) gemm_kernel(
    const float* __restrict__ x,
    const float* __restrict__ Wl,
    const float* __restrict__ Wr,
    int M)
{
    __shared__ __align__(16) float As[2][BK][BM];   // k-major: As[k][row]
    __shared__ __align__(16) float Bs[2][BK][BN];   // Bs[k][col]

    int by = blockIdx.y;                  // 0..3 : col tile over [W_l | W_r]
    const float* W = (by < 2) ? Wl : Wr;
    float*       C = (by < 2) ? g_XL : g_XR;
    int colbase = (by & 1) * BN;
    int row0 = blockIdx.x * BM;

    int tid = threadIdx.x;
    int tx = tid & 15, ty = tid >> 4;     // tx: col group, ty: row group (8 rows)

    // A loader: row = tid & 127, kgroup = tid >> 7 -> k a_kg0..+3 and a_kg0+8..+11
    int a_row = tid & 127;
    int a_kg0 = (tid >> 7) * 4;
    // B loader: k-row = tid >> 4 (0..15), cols (tid&15)*4 and +64
    int b_k = tid >> 4, b_c = (tid & 15) * 4;

    float acc[8][8] = {};
    float4 a_pre0, a_pre1, b_pre0, b_pre1;

    // ---- prefetch k-tile 0 ----
    {
        int grow = row0 + a_row;
        a_pre0 = a_pre1 = make_float4(0.f, 0.f, 0.f, 0.f);
        if (grow < M) {
            a_pre0 = *(const float4*)(x + (size_t)grow * D_IN + a_kg0);
            a_pre1 = *(const float4*)(x + (size_t)grow * D_IN + a_kg0 + 8);
        }
        b_pre0 = *(const float4*)(W + (size_t)b_k * HC + colbase + b_c);
        b_pre1 = *(const float4*)(W + (size_t)b_k * HC + colbase + b_c + 64);
    }
    {
        As[0][a_kg0 + 0][a_row] = a_pre0.x; As[0][a_kg0 + 1][a_row] = a_pre0.y;
        As[0][a_kg0 + 2][a_row] = a_pre0.z; As[0][a_kg0 + 3][a_row] = a_pre0.w;
        As[0][a_kg0 + 8][a_row] = a_pre1.x; As[0][a_kg0 + 9][a_row] = a_pre1.y;
        As[0][a_kg0 +10][a_row] = a_pre1.z; As[0][a_kg0 +11][a_row] = a_pre1.w;
        *(float4*)&Bs[0][b_k][b_c]      = b_pre0;
        *(float4*)&Bs[0][b_k][b_c + 64] = b_pre1;
    }
    __syncthreads();

    const int NT = D_IN / BK;   // 8 k-tiles
#pragma unroll 1
    for (int kt = 0; kt < NT; kt++) {
        int cur = kt & 1, nxt = cur ^ 1;

        if (kt + 1 < NT) {
            int k0 = (kt + 1) * BK;
            int grow = row0 + a_row;
            a_pre0 = a_pre1 = make_float4(0.f, 0.f, 0.f, 0.f);
            if (grow < M) {
                a_pre0 = *(const float4*)(x + (size_t)grow * D_IN + k0 + a_kg0);
                a_pre1 = *(const float4*)(x + (size_t)grow * D_IN + k0 + a_kg0 + 8);
            }
            b_pre0 = *(const float4*)(W + (size_t)(k0 + b_k) * HC + colbase + b_c);
            b_pre1 = *(const float4*)(W + (size_t)(k0 + b_k) * HC + colbase + b_c + 64);
        }

#pragma unroll
        for (int k = 0; k < BK; k++) {
            float4 a0 = *(const float4*)&As[cur][k][ty * 8];
            float4 a1 = *(const float4*)&As[cur][k][ty * 8 + 4];
            float4 b0 = *(const float4*)&Bs[cur][k][tx * 4];
            float4 b1 = *(const float4*)&Bs[cur][k][tx * 4 + 64];
            float a[8] = {a0.x, a0.y, a0.z, a0.w, a1.x, a1.y, a1.z, a1.w};
            float b[8] = {b0.x, b0.y, b0.z, b0.w, b1.x, b1.y, b1.z, b1.w};
#pragma unroll
            for (int i = 0; i < 8; i++)
#pragma unroll
                for (int j = 0; j < 8; j++) acc[i][j] += a[i] * b[j];
        }

        if (kt + 1 < NT) {
            As[nxt][a_kg0 + 0][a_row] = a_pre0.x; As[nxt][a_kg0 + 1][a_row] = a_pre0.y;
            As[nxt][a_kg0 + 2][a_row] = a_pre0.z; As[nxt][a_kg0 + 3][a_row] = a_pre0.w;
            As[nxt][a_kg0 + 8][a_row] = a_pre1.x; As[nxt][a_kg0 + 9][a_row] = a_pre1.y;
            As[nxt][a_kg0 +10][a_row] = a_pre1.z; As[nxt][a_kg0 +11][a_row] = a_pre1.w;
            *(float4*)&Bs[nxt][b_k][b_c]      = b_pre0;
            *(float4*)&Bs[nxt][b_k][b_c + 64] = b_pre1;
            __syncthreads();
        }
    }

#pragma unroll
    for (int i = 0; i < 8; i++) {
        int grow = row0 + ty * 8 + i;
        if (grow < M) {
            float4 v0 = make_float4(acc[i][0], acc[i][1], acc[i][2], acc[i][3]);
            float4 v1 = make_float4(acc[i][4], acc[i][5], acc[i][6], acc[i][7]);
            *(float4*)(C + (size_t)grow * HC + colbase + tx * 4)      = v0;
            *(float4*)(C + (size_t)grow * HC + colbase + tx * 4 + 64) = v1;
        }
    }
}

// ---------------------------------------------------------------------------
// CSR build
// ---------------------------------------------------------------------------
__global__ void init_kernel(int n) {
    int i = blockIdx.x * blockDim.x + threadIdx.x;
    if (i < n) { g_deg[i] = 0; g_cur[i] = 0; }
}

__global__ void count_kernel(const int* __restrict__ dst, int E) {
    int i = blockIdx.x * blockDim.x + threadIdx.x;
    if (i < E) atomicAdd(&g_deg[dst[i]], 1);
}

// Phase 1: per-block inclusive scan of deg (1024/block), emit block sums.
__global__ void __launch_bounds__(1024) scan1_kernel(int n) {
    __shared__ int s[1024];
    int idx = blockIdx.x * 1024 + threadIdx.x;
    int v = (idx < n) ? g_deg[idx] : 0;
    s[threadIdx.x] = v;
    __syncthreads();
#pragma unroll
    for (int off = 1; off < 1024; off <<= 1) {
        int t = (threadIdx.x >= off) ? s[threadIdx.x - off] : 0;
        __syncthreads();
        s[threadIdx.x] += t;
        __syncthreads();
    }
    if (idx < n) g_scan[idx] = s[threadIdx.x];
    if (threadIdx.x == 1023) g_bsum[blockIdx.x] = s[1023];
}

// Phase 2: exclusive scan of block sums (nb <= 64), shared-memory Hillis-Steele.
__global__ void __launch_bounds__(64) scan2_kernel(int nb) {
    __shared__ int s[64];
    int t = threadIdx.x;
    int v0 = (t < nb) ? g_bsum[t] : 0;
    s[t] = v0;
    __syncthreads();
#pragma unroll
    for (int off = 1; off < 64; off <<= 1) {
        int u = (t >= off) ? s[t - off] : 0;
        __syncthreads();
        s[t] += u;
        __syncthreads();
    }
    if (t < nb) g_bpre[t] = s[t] - v0;    // inclusive -> exclusive
}

// Phase 3: add block prefixes, write exclusive offsets.
__global__ void scan3_kernel(int n) {
    int idx = blockIdx.x * 1024 + threadIdx.x;
    if (idx < n) g_offs[idx + 1] = g_scan[idx] + g_bpre[blockIdx.x];
    if (idx == 0) g_offs[0] = 0;
}

__global__ void scatter_kernel(const int* __restrict__ src,
                               const int* __restrict__ dst, int E) {
    int i = blockIdx.x * blockDim.x + threadIdx.x;
    if (i < E) {
        int d = dst[i];
        int pos = g_offs[d] + atomicAdd(&g_cur[d], 1);
        g_esrc[pos] = src[i];
    }
}

// ---------------------------------------------------------------------------
// Single-pass GATv2 aggregation.
// 4 nodes per 256-thread block; 64 threads per node (head = t64>>4, lane
// owns 4 channels via float4). Width-16 shuffle reduction for the per-head
// dot product. Online softmax without max-shift (|e| ~ N(0,~1), fp32-safe):
//   acc += exp(e)*XL[src], den += exp(e); out = mean_h(acc/den) + bias
// Self-loop appended as the (end) iteration.
// ---------------------------------------------------------------------------
__global__ void __launch_bounds__(256) agg_kernel(
    const float* __restrict__ att,
    const float* __restrict__ bias,
    float* __restrict__ out, int N)
{
    int tid = threadIdx.x;
    int nl   = tid >> 6;                  // node within block (0..3)
    int t64  = tid & 63;
    int node = blockIdx.x * 4 + nl;
    int head = t64 >> 4;
    int l16  = t64 & 15;
    int cbase = head * 64 + l16 * 4;

    __shared__ float s[4][4][64];         // [node][head][channel]

    if (node < N) {
        float4 xr4 = *(const float4*)(g_XR + (size_t)node * HC + cbase);
        float4 at4 = *(const float4*)(att + cbase);

        float4 acc = make_float4(0.f, 0.f, 0.f, 0.f);
        float den = 0.f;
        int beg = g_offs[node], end = g_offs[node + 1];

        for (int e = beg; e <= end; e++) {
            int src = (e < end) ? g_esrc[e] : node;   // e==end -> self loop
            float4 xl4 = *(const float4*)(g_XL + (size_t)src * HC + cbase);
            float m0 = xl4.x + xr4.x, m1 = xl4.y + xr4.y;
            float m2 = xl4.z + xr4.z, m3 = xl4.w + xr4.w;
            m0 = (m0 > 0.f) ? m0 : 0.2f * m0;
            m1 = (m1 > 0.f) ? m1 : 0.2f * m1;
            m2 = (m2 > 0.f) ? m2 : 0.2f * m2;
            m3 = (m3 > 0.f) ? m3 : 0.2f * m3;
            float d = m0 * at4.x + m1 * at4.y + m2 * at4.z + m3 * at4.w;
#pragma unroll
            for (int off = 8; off; off >>= 1)
                d += __shfl_xor_sync(0xffffffffu, d, off);
            float w = __expf(d);
            acc.x += w * xl4.x; acc.y += w * xl4.y;
            acc.z += w * xl4.z; acc.w += w * xl4.w;
            den += w;
        }

        float inv = 1.f / den;
        s[nl][head][l16 * 4 + 0] = acc.x * inv;
        s[nl][head][l16 * 4 + 1] = acc.y * inv;
        s[nl][head][l16 * 4 + 2] = acc.z * inv;
        s[nl][head][l16 * 4 + 3] = acc.w * inv;
    }
    __syncthreads();

    // write: thread tid handles node tid>>6, channel tid&63
    int c = tid & 63;
    if (node < N) {
        float v = 0.25f * (s[nl][0][c] + s[nl][1][c] + s[nl][2][c] + s[nl][3][c])
                + bias[c];
        out[(size_t)node * 64 + c] = v;
    }
}

// ---------------------------------------------------------------------------
extern "C" void kernel_launch(void* const* d_in, const int* in_sizes, int n_in,
                              void* d_out, int out_size)
{
    const float* x    = (const float*)d_in[0];
    const int*   ei   = (const int*)d_in[1];
    const float* Wl   = (const float*)d_in[2];
    const float* Wr   = (const float*)d_in[3];
    const float* att  = (const float*)d_in[4];
    const float* bias = (const float*)d_in[5];
    float*       out  = (float*)d_out;

    int N = in_sizes[0] / D_IN;
    int E = in_sizes[1] / 2;
    const int* src = ei;
    const int* dst = ei + E;

    init_kernel<<<(N + 255) / 256, 256>>>(N);

    dim3 ggrid((N + BM - 1) / BM, 4);
    gemm_kernel<<<ggrid, 256>>>(x, Wl, Wr, N);

    count_kernel<<<(E + 255) / 256, 256>>>(dst, E);

    int nb = (N + 1023) / 1024;
    scan1_kernel<<<nb, 1024>>>(N);
    scan2_kernel<<<1, 64>>>(nb);
    scan3_kernel<<<nb, 1024>>>(N);

    scatter_kernel<<<(E + 255) / 256, 256>>>(src, dst, E);

    agg_kernel<<<(N + 3) / 4, 256>>>(att, bias, out, N);
}

// round 6
// speedup vs baseline: 1.3075x; 1.0345x over previous
#include <cuda_runtime.h>
#include <cstdint>

#define D_IN 128
#define HC 256          // HEADS * C_OUT
#define N_NODES_MAX 50000
#define E_MAX 800000

#define BM 128
#define BN 128
#define KC 16           // k-chunk in smem
#define BMP 136         // padded (pad 8 -> conflict-free frag LDS)
#define BNP 136

// Scratch (allocation-free rule: __device__ globals)
__device__ float g_XL[(size_t)N_NODES_MAX * HC];   // x @ W_l, [N,256]
__device__ float g_XR[(size_t)N_NODES_MAX * HC];   // x @ W_r, [N,256]
__device__ int   g_deg [N_NODES_MAX];
__device__ int   g_offs[N_NODES_MAX + 1];
__device__ int   g_cur [N_NODES_MAX];
__device__ int   g_esrc[E_MAX];                    // CSR: sources grouped by dst
__device__ int   g_scan[N_NODES_MAX];              // block-inclusive scans
__device__ int   g_bsum[64];
__device__ int   g_bpre[64];

// ---------------------------------------------------------------------------
// tf32 helpers
// ---------------------------------------------------------------------------
__device__ __forceinline__ uint32_t f2tf32(float f) {
    uint32_t r;
    asm("cvt.rna.tf32.f32 %0, %1;" : "=r"(r) : "f"(f));
    return r;
}
__device__ __forceinline__ void split_tf32(float v, uint32_t& hi, uint32_t& lo) {
    hi = f2tf32(v);
    lo = f2tf32(v - __uint_as_float(hi));
}
__device__ __forceinline__ void mma_tf32(float* d, const uint32_t* a, const uint32_t* b) {
    asm volatile(
        "mma.sync.aligned.m16n8k8.row.col.f32.tf32.tf32.f32 "
        "{%0,%1,%2,%3}, {%4,%5,%6,%7}, {%8,%9}, {%0,%1,%2,%3};"
        : "+f"(d[0]), "+f"(d[1]), "+f"(d[2]), "+f"(d[3])
        : "r"(a[0]), "r"(a[1]), "r"(a[2]), "r"(a[3]), "r"(b[0]), "r"(b[1]));
}

// ---------------------------------------------------------------------------
// Fused dual-output GEMM on tensor cores (split-tf32, 3-term):
//   XL = x @ W_l, XR = x @ W_r.  D = Ah*Bh + Ah*Bl + Al*Bh  (err ~ eps^2)
// CTA: 128x128 tile, 8 warps (64x32 warp tile), K chunked by 16.
// ---------------------------------------------------------------------------
__global__ void __launch_bounds__(256) gemm_kernel(
    const float* __restrict__ x,
    const float* __restrict__ Wl,
    const float* __restrict__ Wr,
    int M)
{
    __shared__ uint32_t As_hi[KC][BMP];
    __shared__ uint32_t As_lo[KC][BMP];
    __shared__ uint32_t Bs_hi[KC][BNP];
    __shared__ uint32_t Bs_lo[KC][BNP];

    int by = blockIdx.y;                  // 0,1: W_l halves; 2,3: W_r halves
    const float* W = (by < 2) ? Wl : Wr;
    float*       C = (by < 2) ? g_XL : g_XR;
    int colbase = (by & 1) * BN;
    int row0 = blockIdx.x * BM;

    int tid  = threadIdx.x;
    int warp = tid >> 5, lane = tid & 31;
    int wm = warp >> 2, wn = warp & 3;    // warp tile: rows wm*64, cols wn*32
    int lr = lane >> 2, lc = lane & 3;    // fragment lane decomposition

    // A loader: row = tid&127, k-offset = (tid>>7)*8, two float4
    int a_row = tid & 127;
    int a_k   = (tid >> 7) * 8;

    float acc[4][4][4];
#pragma unroll
    for (int i = 0; i < 4; i++)
#pragma unroll
        for (int j = 0; j < 4; j++)
#pragma unroll
            for (int q = 0; q < 4; q++) acc[i][j][q] = 0.f;

    const int NCH = D_IN / KC;            // 8 chunks
#pragma unroll 1
    for (int kc = 0; kc < NCH; kc++) {
        if (kc) __syncthreads();

        // ---- load A chunk [128 rows x 16 k], convert, store k-major hi/lo ----
        {
            int grow = row0 + a_row;
            const float* ap = x + (size_t)grow * D_IN + kc * KC + a_k;
#pragma unroll
            for (int half = 0; half < 2; half++) {
                float4 v = make_float4(0.f, 0.f, 0.f, 0.f);
                if (grow < M) v = *(const float4*)(ap + half * 4);
                uint32_t h, l;
                int kk = a_k + half * 4;
                split_tf32(v.x, h, l); As_hi[kk+0][a_row] = h; As_lo[kk+0][a_row] = l;
                split_tf32(v.y, h, l); As_hi[kk+1][a_row] = h; As_lo[kk+1][a_row] = l;
                split_tf32(v.z, h, l); As_hi[kk+2][a_row] = h; As_lo[kk+2][a_row] = l;
                split_tf32(v.w, h, l); As_hi[kk+3][a_row] = h; As_lo[kk+3][a_row] = l;
            }
        }
        // ---- load B chunk [16 k x 128 cols], convert, store hi/lo ----
        {
#pragma unroll
            for (int q = 0; q < 2; q++) {
                int j = tid + q * 256;            // 512 float4 jobs
                int k_r = j >> 5;                 // 0..15
                int n4  = (j & 31) * 4;
                float4 v = *(const float4*)(W + (size_t)(kc * KC + k_r) * HC + colbase + n4);
                uint32_t h0,l0,h1,l1,h2,l2,h3,l3;
                split_tf32(v.x, h0, l0); split_tf32(v.y, h1, l1);
                split_tf32(v.z, h2, l2); split_tf32(v.w, h3, l3);
                Bs_hi[k_r][n4+0]=h0; Bs_hi[k_r][n4+1]=h1; Bs_hi[k_r][n4+2]=h2; Bs_hi[k_r][n4+3]=h3;
                Bs_lo[k_r][n4+0]=l0; Bs_lo[k_r][n4+1]=l1; Bs_lo[k_r][n4+2]=l2; Bs_lo[k_r][n4+3]=l3;
            }
        }
        __syncthreads();

        // ---- compute: 2 k-steps of 8 ----
#pragma unroll
        for (int ks = 0; ks < KC / 8; ks++) {
            int k0 = ks * 8;
            uint32_t a_hi[4][4], a_lo[4][4], b_hi[4][2], b_lo[4][2];
            int c0 = k0 + lc;
#pragma unroll
            for (int mt = 0; mt < 4; mt++) {
                int r = wm * 64 + mt * 16 + lr;
                a_hi[mt][0] = As_hi[c0  ][r];   a_hi[mt][1] = As_hi[c0  ][r+8];
                a_hi[mt][2] = As_hi[c0+4][r];   a_hi[mt][3] = As_hi[c0+4][r+8];
                a_lo[mt][0] = As_lo[c0  ][r];   a_lo[mt][1] = As_lo[c0  ][r+8];
                a_lo[mt][2] = As_lo[c0+4][r];   a_lo[mt][3] = As_lo[c0+4][r+8];
            }
#pragma unroll
            for (int nt = 0; nt < 4; nt++) {
                int n = wn * 32 + nt * 8 + lr;
                b_hi[nt][0] = Bs_hi[c0  ][n];   b_hi[nt][1] = Bs_hi[c0+4][n];
                b_lo[nt][0] = Bs_lo[c0  ][n];   b_lo[nt][1] = Bs_lo[c0+4][n];
            }
#pragma unroll
            for (int mt = 0; mt < 4; mt++)
#pragma unroll
                for (int nt = 0; nt < 4; nt++) {
                    mma_tf32(acc[mt][nt], a_hi[mt], b_hi[nt]);
                    mma_tf32(acc[mt][nt], a_hi[mt], b_lo[nt]);
                    mma_tf32(acc[mt][nt], a_lo[mt], b_hi[nt]);
                }
        }
    }

    // ---- epilogue: write fragments to C ----
#pragma unroll
    for (int mt = 0; mt < 4; mt++) {
        int r_lo = row0 + wm * 64 + mt * 16 + lr;
        int r_hi = r_lo + 8;
#pragma unroll
        for (int nt = 0; nt < 4; nt++) {
            int col = colbase + wn * 32 + nt * 8 + lc * 2;
            if (r_lo < M)
                *(float2*)(C + (size_t)r_lo * HC + col) =
                    make_float2(acc[mt][nt][0], acc[mt][nt][1]);
            if (r_hi < M)
                *(float2*)(C + (size_t)r_hi * HC + col) =
                    make_float2(acc[mt][nt][2], acc[mt][nt][3]);
        }
    }
}

// ---------------------------------------------------------------------------
// CSR build
// ---------------------------------------------------------------------------
__global__ void init_kernel(int n) {
    int i = blockIdx.x * blockDim.x + threadIdx.x;
    if (i < n) { g_deg[i] = 0; g_cur[i] = 0; }
}

__global__ void count_kernel(const int* __restrict__ dst, int E) {
    int i = blockIdx.x * blockDim.x + threadIdx.x;
    if (i < E) atomicAdd(&g_deg[dst[i]], 1);
}

// Phase 1: per-block inclusive scan of deg (1024/block), emit block sums.
__global__ void __launch_bounds__(1024) scan1_kernel(int n) {
    __shared__ int s[1024];
    int idx = blockIdx.x * 1024 + threadIdx.x;
    int v = (idx < n) ? g_deg[idx] : 0;
    s[threadIdx.x] = v;
    __syncthreads();
#pragma unroll
    for (int off = 1; off < 1024; off <<= 1) {
        int t = (threadIdx.x >= off) ? s[threadIdx.x - off] : 0;
        __syncthreads();
        s[threadIdx.x] += t;
        __syncthreads();
    }
    if (idx < n) g_scan[idx] = s[threadIdx.x];
    if (threadIdx.x == 1023) g_bsum[blockIdx.x] = s[1023];
}

// Phase 2: exclusive scan of block sums (nb <= 64), shared-memory Hillis-Steele.
__global__ void __launch_bounds__(64) scan2_kernel(int nb) {
    __shared__ int s[64];
    int t = threadIdx.x;
    int v0 = (t < nb) ? g_bsum[t] : 0;
    s[t] = v0;
    __syncthreads();
#pragma unroll
    for (int off = 1; off < 64; off <<= 1) {
        int u = (t >= off) ? s[t - off] : 0;
        __syncthreads();
        s[t] += u;
        __syncthreads();
    }
    if (t < nb) g_bpre[t] = s[t] - v0;    // inclusive -> exclusive
}

// Phase 3: add block prefixes, write exclusive offsets.
__global__ void scan3_kernel(int n) {
    int idx = blockIdx.x * 1024 + threadIdx.x;
    if (idx < n) g_offs[idx + 1] = g_scan[idx] + g_bpre[blockIdx.x];
    if (idx == 0) g_offs[0] = 0;
}

__global__ void scatter_kernel(const int* __restrict__ src,
                               const int* __restrict__ dst, int E) {
    int i = blockIdx.x * blockDim.x + threadIdx.x;
    if (i < E) {
        int d = dst[i];
        int pos = g_offs[d] + atomicAdd(&g_cur[d], 1);
        g_esrc[pos] = src[i];
    }
}

// ---------------------------------------------------------------------------
// Single-pass GATv2 aggregation.
// 4 nodes per 256-thread block; 64 threads per node (head = t64>>4, lane
// owns 4 channels via float4). Width-16 shuffle reduction per head.
// Online softmax without max-shift (|e| ~ N(0,~1), fp32-safe):
//   acc += exp(e)*XL[src], den += exp(e); out = mean_h(acc/den) + bias
// ---------------------------------------------------------------------------
__global__ void __launch_bounds__(256) agg_kernel(
    const float* __restrict__ att,
    const float* __restrict__ bias,
    float* __restrict__ out, int N)
{
    int tid = threadIdx.x;
    int nl   = tid >> 6;                  // node within block (0..3)
    int t64  = tid & 63;
    int node = blockIdx.x * 4 + nl;
    int head = t64 >> 4;
    int l16  = t64 & 15;
    int cbase = head * 64 + l16 * 4;

    __shared__ float s[4][4][64];         // [node][head][channel]

    if (node < N) {
        float4 xr4 = *(const float4*)(g_XR + (size_t)node * HC + cbase);
        float4 at4 = *(const float4*)(att + cbase);

        float4 acc = make_float4(0.f, 0.f, 0.f, 0.f);
        float den = 0.f;
        int beg = g_offs[node], end = g_offs[node + 1];

        for (int e = beg; e <= end; e++) {
            int src = (e < end) ? g_esrc[e] : node;   // e==end -> self loop
            float4 xl4 = *(const float4*)(g_XL + (size_t)src * HC + cbase);
            float m0 = xl4.x + xr4.x, m1 = xl4.y + xr4.y;
            float m2 = xl4.z + xr4.z, m3 = xl4.w + xr4.w;
            m0 = (m0 > 0.f) ? m0 : 0.2f * m0;
            m1 = (m1 > 0.f) ? m1 : 0.2f * m1;
            m2 = (m2 > 0.f) ? m2 : 0.2f * m2;
            m3 = (m3 > 0.f) ? m3 : 0.2f * m3;
            float d = m0 * at4.x + m1 * at4.y + m2 * at4.z + m3 * at4.w;
#pragma unroll
            for (int off = 8; off; off >>= 1)
                d += __shfl_xor_sync(0xffffffffu, d, off);
            float w = __expf(d);
            acc.x += w * xl4.x; acc.y += w * xl4.y;
            acc.z += w * xl4.z; acc.w += w * xl4.w;
            den += w;
        }

        float inv = 1.f / den;
        s[nl][head][l16 * 4 + 0] = acc.x * inv;
        s[nl][head][l16 * 4 + 1] = acc.y * inv;
        s[nl][head][l16 * 4 + 2] = acc.z * inv;
        s[nl][head][l16 * 4 + 3] = acc.w * inv;
    }
    __syncthreads();

    int c = tid & 63;
    if (node < N) {
        float v = 0.25f * (s[nl][0][c] + s[nl][1][c] + s[nl][2][c] + s[nl][3][c])
                + bias[c];
        out[(size_t)node * 64 + c] = v;
    }
}

// ---------------------------------------------------------------------------
extern "C" void kernel_launch(void* const* d_in, const int* in_sizes, int n_in,
                              void* d_out, int out_size)
{
    const float* x    = (const float*)d_in[0];
    const int*   ei   = (const int*)d_in[1];
    const float* Wl   = (const float*)d_in[2];
    const float* Wr   = (const float*)d_in[3];
    const float* att  = (const float*)d_in[4];
    const float* bias = (const float*)d_in[5];
    float*       out  = (float*)d_out;

    int N = in_sizes[0] / D_IN;
    int E = in_sizes[1] / 2;
    const int* src = ei;
    const int* dst = ei + E;

    init_kernel<<<(N + 255) / 256, 256>>>(N);

    dim3 ggrid((N + BM - 1) / BM, 4);
    gemm_kernel<<<ggrid, 256>>>(x, Wl, Wr, N);

    count_kernel<<<(E + 255) / 256, 256>>>(dst, E);

    int nb = (N + 1023) / 1024;
    scan1_kernel<<<nb, 1024>>>(N);
    scan2_kernel<<<1, 64>>>(nb);
    scan3_kernel<<<nb, 1024>>>(N);

    scatter_kernel<<<(E + 255) / 256, 256>>>(src, dst, E);

    agg_kernel<<<(N + 3) / 4, 256>>>(att, bias, out, N);
}

// round 7
// speedup vs baseline: 1.3098x; 1.0017x over previous
#include <cuda_runtime.h>
#include <cstdint>

#define D_IN 128
#define HC 256          // HEADS * C_OUT
#define N_NODES_MAX 50000
#define E_MAX 800000

#define BM 128
#define BN 128
#define KC 16           // k-chunk in smem
#define BMP 136         // padded (pad 8 -> conflict-free frag LDS)
#define BNP 136

// Scratch (allocation-free rule: __device__ globals)
__device__ float g_XL[(size_t)N_NODES_MAX * HC];   // x @ W_l, [N,256]
__device__ float g_XR[(size_t)N_NODES_MAX * HC];   // x @ W_r, [N,256]
__device__ int   g_deg [N_NODES_MAX];
__device__ int   g_offs[N_NODES_MAX + 1];
__device__ int   g_cur [N_NODES_MAX];
__device__ int   g_esrc[E_MAX];                    // CSR: sources grouped by dst
__device__ int   g_scan[N_NODES_MAX];              // block-inclusive scans
__device__ int   g_bsum[64];
__device__ int   g_bpre[64];

// ---------------------------------------------------------------------------
// tf32 helpers
// ---------------------------------------------------------------------------
__device__ __forceinline__ uint32_t f2tf32(float f) {
    uint32_t r;
    asm("cvt.rna.tf32.f32 %0, %1;" : "=r"(r) : "f"(f));
    return r;
}
__device__ __forceinline__ void split_tf32(float v, uint32_t& hi, uint32_t& lo) {
    hi = f2tf32(v);
    lo = f2tf32(v - __uint_as_float(hi));
}
__device__ __forceinline__ void mma_tf32(float* d, const uint32_t* a, const uint32_t* b) {
    asm volatile(
        "mma.sync.aligned.m16n8k8.row.col.f32.tf32.tf32.f32 "
        "{%0,%1,%2,%3}, {%4,%5,%6,%7}, {%8,%9}, {%0,%1,%2,%3};"
        : "+f"(d[0]), "+f"(d[1]), "+f"(d[2]), "+f"(d[3])
        : "r"(a[0]), "r"(a[1]), "r"(a[2]), "r"(a[3]), "r"(b[0]), "r"(b[1]));
}

// ---------------------------------------------------------------------------
// Fused dual-output GEMM on tensor cores (split-tf32, 3-term):
//   XL = x @ W_l, XR = x @ W_r.  D = Ah*Bh + Ah*Bl + Al*Bh  (err ~ eps^2)
// CTA: 128x128 tile, 8 warps (64x32 warp tile), K chunked by 16.
// ---------------------------------------------------------------------------
__global__ void __launch_bounds__(256) gemm_kernel(
    const float* __restrict__ x,
    const float* __restrict__ Wl,
    const float* __restrict__ Wr,
    int M)
{
    __shared__ uint32_t As_hi[KC][BMP];
    __shared__ uint32_t As_lo[KC][BMP];
    __shared__ uint32_t Bs_hi[KC][BNP];
    __shared__ uint32_t Bs_lo[KC][BNP];

    int by = blockIdx.y;                  // 0,1: W_l halves; 2,3: W_r halves
    const float* W = (by < 2) ? Wl : Wr;
    float*       C = (by < 2) ? g_XL : g_XR;
    int colbase = (by & 1) * BN;
    int row0 = blockIdx.x * BM;

    int tid  = threadIdx.x;
    int warp = tid >> 5, lane = tid & 31;
    int wm = warp >> 2, wn = warp & 3;    // warp tile: rows wm*64, cols wn*32
    int lr = lane >> 2, lc = lane & 3;    // fragment lane decomposition

    // A loader: row = tid&127, k-offset = (tid>>7)*8, two float4
    int a_row = tid & 127;
    int a_k   = (tid >> 7) * 8;

    float acc[4][4][4];
#pragma unroll
    for (int i = 0; i < 4; i++)
#pragma unroll
        for (int j = 0; j < 4; j++)
#pragma unroll
            for (int q = 0; q < 4; q++) acc[i][j][q] = 0.f;

    const int NCH = D_IN / KC;            // 8 chunks
#pragma unroll 1
    for (int kc = 0; kc < NCH; kc++) {
        if (kc) __syncthreads();

        // ---- load A chunk [128 rows x 16 k], convert, store k-major hi/lo ----
        {
            int grow = row0 + a_row;
            const float* ap = x + (size_t)grow * D_IN + kc * KC + a_k;
#pragma unroll
            for (int half = 0; half < 2; half++) {
                float4 v = make_float4(0.f, 0.f, 0.f, 0.f);
                if (grow < M) v = *(const float4*)(ap + half * 4);
                uint32_t h, l;
                int kk = a_k + half * 4;
                split_tf32(v.x, h, l); As_hi[kk+0][a_row] = h; As_lo[kk+0][a_row] = l;
                split_tf32(v.y, h, l); As_hi[kk+1][a_row] = h; As_lo[kk+1][a_row] = l;
                split_tf32(v.z, h, l); As_hi[kk+2][a_row] = h; As_lo[kk+2][a_row] = l;
                split_tf32(v.w, h, l); As_hi[kk+3][a_row] = h; As_lo[kk+3][a_row] = l;
            }
        }
        // ---- load B chunk [16 k x 128 cols], convert, store hi/lo ----
        {
#pragma unroll
            for (int q = 0; q < 2; q++) {
                int j = tid + q * 256;            // 512 float4 jobs
                int k_r = j >> 5;                 // 0..15
                int n4  = (j & 31) * 4;
                float4 v = *(const float4*)(W + (size_t)(kc * KC + k_r) * HC + colbase + n4);
                uint32_t h0,l0,h1,l1,h2,l2,h3,l3;
                split_tf32(v.x, h0, l0); split_tf32(v.y, h1, l1);
                split_tf32(v.z, h2, l2); split_tf32(v.w, h3, l3);
                Bs_hi[k_r][n4+0]=h0; Bs_hi[k_r][n4+1]=h1; Bs_hi[k_r][n4+2]=h2; Bs_hi[k_r][n4+3]=h3;
                Bs_lo[k_r][n4+0]=l0; Bs_lo[k_r][n4+1]=l1; Bs_lo[k_r][n4+2]=l2; Bs_lo[k_r][n4+3]=l3;
            }
        }
        __syncthreads();

        // ---- compute: 2 k-steps of 8 ----
#pragma unroll
        for (int ks = 0; ks < KC / 8; ks++) {
            int k0 = ks * 8;
            uint32_t a_hi[4][4], a_lo[4][4], b_hi[4][2], b_lo[4][2];
            int c0 = k0 + lc;
#pragma unroll
            for (int mt = 0; mt < 4; mt++) {
                int r = wm * 64 + mt * 16 + lr;
                a_hi[mt][0] = As_hi[c0  ][r];   a_hi[mt][1] = As_hi[c0  ][r+8];
                a_hi[mt][2] = As_hi[c0+4][r];   a_hi[mt][3] = As_hi[c0+4][r+8];
                a_lo[mt][0] = As_lo[c0  ][r];   a_lo[mt][1] = As_lo[c0  ][r+8];
                a_lo[mt][2] = As_lo[c0+4][r];   a_lo[mt][3] = As_lo[c0+4][r+8];
            }
#pragma unroll
            for (int nt = 0; nt < 4; nt++) {
                int n = wn * 32 + nt * 8 + lr;
                b_hi[nt][0] = Bs_hi[c0  ][n];   b_hi[nt][1] = Bs_hi[c0+4][n];
                b_lo[nt][0] = Bs_lo[c0  ][n];   b_lo[nt][1] = Bs_lo[c0+4][n];
            }
#pragma unroll
            for (int mt = 0; mt < 4; mt++)
#pragma unroll
                for (int nt = 0; nt < 4; nt++) {
                    mma_tf32(acc[mt][nt], a_hi[mt], b_hi[nt]);
                    mma_tf32(acc[mt][nt], a_hi[mt], b_lo[nt]);
                    mma_tf32(acc[mt][nt], a_lo[mt], b_hi[nt]);
                }
        }
    }

    // ---- epilogue: write fragments to C ----
#pragma unroll
    for (int mt = 0; mt < 4; mt++) {
        int r_lo = row0 + wm * 64 + mt * 16 + lr;
        int r_hi = r_lo + 8;
#pragma unroll
        for (int nt = 0; nt < 4; nt++) {
            int col = colbase + wn * 32 + nt * 8 + lc * 2;
            if (r_lo < M)
                *(float2*)(C + (size_t)r_lo * HC + col) =
                    make_float2(acc[mt][nt][0], acc[mt][nt][1]);
            if (r_hi < M)
                *(float2*)(C + (size_t)r_hi * HC + col) =
                    make_float2(acc[mt][nt][2], acc[mt][nt][3]);
        }
    }
}

// ---------------------------------------------------------------------------
// CSR build
// ---------------------------------------------------------------------------
__global__ void init_kernel(int n) {
    int i = blockIdx.x * blockDim.x + threadIdx.x;
    if (i < n) { g_deg[i] = 0; g_cur[i] = 0; }
}

__global__ void count_kernel(const int* __restrict__ dst, int E) {
    int i = blockIdx.x * blockDim.x + threadIdx.x;
    if (i < E) atomicAdd(&g_deg[dst[i]], 1);
}

// Phase 1: per-block inclusive scan of deg (1024/block), emit block sums.
__global__ void __launch_bounds__(1024) scan1_kernel(int n) {
    __shared__ int s[1024];
    int idx = blockIdx.x * 1024 + threadIdx.x;
    int v = (idx < n) ? g_deg[idx] : 0;
    s[threadIdx.x] = v;
    __syncthreads();
#pragma unroll
    for (int off = 1; off < 1024; off <<= 1) {
        int t = (threadIdx.x >= off) ? s[threadIdx.x - off] : 0;
        __syncthreads();
        s[threadIdx.x] += t;
        __syncthreads();
    }
    if (idx < n) g_scan[idx] = s[threadIdx.x];
    if (threadIdx.x == 1023) g_bsum[blockIdx.x] = s[1023];
}

// Phase 2: exclusive scan of block sums (nb <= 64), shared-memory Hillis-Steele.
__global__ void __launch_bounds__(64) scan2_kernel(int nb) {
    __shared__ int s[64];
    int t = threadIdx.x;
    int v0 = (t < nb) ? g_bsum[t] : 0;
    s[t] = v0;
    __syncthreads();
#pragma unroll
    for (int off = 1; off < 64; off <<= 1) {
        int u = (t >= off) ? s[t - off] : 0;
        __syncthreads();
        s[t] += u;
        __syncthreads();
    }
    if (t < nb) g_bpre[t] = s[t] - v0;    // inclusive -> exclusive
}

// Phase 3: add block prefixes, write exclusive offsets.
__global__ void scan3_kernel(int n) {
    int idx = blockIdx.x * 1024 + threadIdx.x;
    if (idx < n) g_offs[idx + 1] = g_scan[idx] + g_bpre[blockIdx.x];
    if (idx == 0) g_offs[0] = 0;
}

__global__ void scatter_kernel(const int* __restrict__ src,
                               const int* __restrict__ dst, int E) {
    int i = blockIdx.x * blockDim.x + threadIdx.x;
    if (i < E) {
        int d = dst[i];
        int pos = g_offs[d] + atomicAdd(&g_cur[d], 1);
        g_esrc[pos] = src[i];
    }
}

// ---------------------------------------------------------------------------
// Single-pass GATv2 aggregation.
// 4 nodes per 256-thread block; 64 threads per node (head = t64>>4, lane
// owns 4 channels via float4). Width-16 shuffle reduction per head.
// Online softmax without max-shift (|e| ~ N(0,~1), fp32-safe):
//   acc += exp(e)*XL[src], den += exp(e); out = mean_h(acc/den) + bias
// ---------------------------------------------------------------------------
__global__ void __launch_bounds__(256) agg_kernel(
    const float* __restrict__ att,
    const float* __restrict__ bias,
    float* __restrict__ out, int N)
{
    int tid = threadIdx.x;
    int nl   = tid >> 6;                  // node within block (0..3)
    int t64  = tid & 63;
    int node = blockIdx.x * 4 + nl;
    int head = t64 >> 4;
    int l16  = t64 & 15;
    int cbase = head * 64 + l16 * 4;

    __shared__ float s[4][4][64];         // [node][head][channel]

    if (node < N) {
        float4 xr4 = *(const float4*)(g_XR + (size_t)node * HC + cbase);
        float4 at4 = *(const float4*)(att + cbase);

        float4 acc = make_float4(0.f, 0.f, 0.f, 0.f);
        float den = 0.f;
        int beg = g_offs[node], end = g_offs[node + 1];

        for (int e = beg; e <= end; e++) {
            int src = (e < end) ? g_esrc[e] : node;   // e==end -> self loop
            float4 xl4 = *(const float4*)(g_XL + (size_t)src * HC + cbase);
            float m0 = xl4.x + xr4.x, m1 = xl4.y + xr4.y;
            float m2 = xl4.z + xr4.z, m3 = xl4.w + xr4.w;
            m0 = (m0 > 0.f) ? m0 : 0.2f * m0;
            m1 = (m1 > 0.f) ? m1 : 0.2f * m1;
            m2 = (m2 > 0.f) ? m2 : 0.2f * m2;
            m3 = (m3 > 0.f) ? m3 : 0.2f * m3;
            float d = m0 * at4.x + m1 * at4.y + m2 * at4.z + m3 * at4.w;
#pragma unroll
            for (int off = 8; off; off >>= 1)
                d += __shfl_xor_sync(0xffffffffu, d, off);
            float w = __expf(d);
            acc.x += w * xl4.x; acc.y += w * xl4.y;
            acc.z += w * xl4.z; acc.w += w * xl4.w;
            den += w;
        }

        float inv = 1.f / den;
        s[nl][head][l16 * 4 + 0] = acc.x * inv;
        s[nl][head][l16 * 4 + 1] = acc.y * inv;
        s[nl][head][l16 * 4 + 2] = acc.z * inv;
        s[nl][head][l16 * 4 + 3] = acc.w * inv;
    }
    __syncthreads();

    int c = tid & 63;
    if (node < N) {
        float v = 0.25f * (s[nl][0][c] + s[nl][1][c] + s[nl][2][c] + s[nl][3][c])
                + bias[c];
        out[(size_t)node * 64 + c] = v;
    }
}

// ---------------------------------------------------------------------------
extern "C" void kernel_launch(void* const* d_in, const int* in_sizes, int n_in,
                              void* d_out, int out_size)
{
    const float* x    = (const float*)d_in[0];
    const int*   ei   = (const int*)d_in[1];
    const float* Wl   = (const float*)d_in[2];
    const float* Wr   = (const float*)d_in[3];
    const float* att  = (const float*)d_in[4];
    const float* bias = (const float*)d_in[5];
    float*       out  = (float*)d_out;

    int N = in_sizes[0] / D_IN;
    int E = in_sizes[1] / 2;
    const int* src = ei;
    const int* dst = ei + E;

    init_kernel<<<(N + 255) / 256, 256>>>(N);

    dim3 ggrid((N + BM - 1) / BM, 4);
    gemm_kernel<<<ggrid, 256>>>(x, Wl, Wr, N);

    count_kernel<<<(E + 255) / 256, 256>>>(dst, E);

    int nb = (N + 1023) / 1024;
    scan1_kernel<<<nb, 1024>>>(N);
    scan2_kernel<<<1, 64>>>(nb);
    scan3_kernel<<<nb, 1024>>>(N);

    scatter_kernel<<<(E + 255) / 256, 256>>>(src, dst, E);

    agg_kernel<<<(N + 3) / 4, 256>>>(att, bias, out, N);
}

// round 8
// speedup vs baseline: 1.3104x; 1.0005x over previous
#include <cuda_runtime.h>
#include <cstdint>

#define D_IN 128
#define HC 256          // HEADS * C_OUT
#define N_NODES_MAX 50000
#define E_MAX 800000

#define BM 128
#define BN 128
#define KC 16           // k-chunk in smem
#define BMP 136         // padded (pad 8 -> conflict-free frag LDS)
#define BNP 136

// Scratch (allocation-free rule: __device__ globals)
__device__ float g_XL[(size_t)N_NODES_MAX * HC];   // x @ W_l, [N,256]
__device__ float g_XR[(size_t)N_NODES_MAX * HC];   // x @ W_r, [N,256]
__device__ int   g_deg [N_NODES_MAX];
__device__ int   g_offs[N_NODES_MAX + 1];
__device__ int   g_cur [N_NODES_MAX];
__device__ int   g_esrc[E_MAX];                    // CSR: sources grouped by dst
__device__ int   g_scan[N_NODES_MAX];              // block-inclusive scans
__device__ int   g_bsum[64];
__device__ int   g_bpre[64];

// ---------------------------------------------------------------------------
// tf32 helpers
// ---------------------------------------------------------------------------
__device__ __forceinline__ uint32_t f2tf32(float f) {
    uint32_t r;
    asm("cvt.rna.tf32.f32 %0, %1;" : "=r"(r) : "f"(f));
    return r;
}
__device__ __forceinline__ void split_tf32(float v, uint32_t& hi, uint32_t& lo) {
    hi = f2tf32(v);
    lo = f2tf32(v - __uint_as_float(hi));
}
__device__ __forceinline__ void mma_tf32(float* d, const uint32_t* a, const uint32_t* b) {
    asm volatile(
        "mma.sync.aligned.m16n8k8.row.col.f32.tf32.tf32.f32 "
        "{%0,%1,%2,%3}, {%4,%5,%6,%7}, {%8,%9}, {%0,%1,%2,%3};"
        : "+f"(d[0]), "+f"(d[1]), "+f"(d[2]), "+f"(d[3])
        : "r"(a[0]), "r"(a[1]), "r"(a[2]), "r"(a[3]), "r"(b[0]), "r"(b[1]));
}

// ---------------------------------------------------------------------------
// Fused dual-output GEMM on tensor cores (split-tf32, 3-term):
//   XL = x @ W_l, XR = x @ W_r.  D = Ah*Bh + Ah*Bl + Al*Bh  (err ~ eps^2)
// CTA: 128x128 tile, 8 warps (64x32 warp tile), K chunked by 16.
// ---------------------------------------------------------------------------
__global__ void __launch_bounds__(256) gemm_kernel(
    const float* __restrict__ x,
    const float* __restrict__ Wl,
    const float* __restrict__ Wr,
    int M)
{
    __shared__ uint32_t As_hi[KC][BMP];
    __shared__ uint32_t As_lo[KC][BMP];
    __shared__ uint32_t Bs_hi[KC][BNP];
    __shared__ uint32_t Bs_lo[KC][BNP];

    int by = blockIdx.y;                  // 0,1: W_l halves; 2,3: W_r halves
    const float* W = (by < 2) ? Wl : Wr;
    float*       C = (by < 2) ? g_XL : g_XR;
    int colbase = (by & 1) * BN;
    int row0 = blockIdx.x * BM;

    int tid  = threadIdx.x;
    int warp = tid >> 5, lane = tid & 31;
    int wm = warp >> 2, wn = warp & 3;    // warp tile: rows wm*64, cols wn*32
    int lr = lane >> 2, lc = lane & 3;    // fragment lane decomposition

    // A loader: row = tid&127, k-offset = (tid>>7)*8, two float4
    int a_row = tid & 127;
    int a_k   = (tid >> 7) * 8;

    float acc[4][4][4];
#pragma unroll
    for (int i = 0; i < 4; i++)
#pragma unroll
        for (int j = 0; j < 4; j++)
#pragma unroll
            for (int q = 0; q < 4; q++) acc[i][j][q] = 0.f;

    const int NCH = D_IN / KC;            // 8 chunks
#pragma unroll 1
    for (int kc = 0; kc < NCH; kc++) {
        if (kc) __syncthreads();

        // ---- load A chunk [128 rows x 16 k], convert, store k-major hi/lo ----
        {
            int grow = row0 + a_row;
            const float* ap = x + (size_t)grow * D_IN + kc * KC + a_k;
#pragma unroll
            for (int half = 0; half < 2; half++) {
                float4 v = make_float4(0.f, 0.f, 0.f, 0.f);
                if (grow < M) v = *(const float4*)(ap + half * 4);
                uint32_t h, l;
                int kk = a_k + half * 4;
                split_tf32(v.x, h, l); As_hi[kk+0][a_row] = h; As_lo[kk+0][a_row] = l;
                split_tf32(v.y, h, l); As_hi[kk+1][a_row] = h; As_lo[kk+1][a_row] = l;
                split_tf32(v.z, h, l); As_hi[kk+2][a_row] = h; As_lo[kk+2][a_row] = l;
                split_tf32(v.w, h, l); As_hi[kk+3][a_row] = h; As_lo[kk+3][a_row] = l;
            }
        }
        // ---- load B chunk [16 k x 128 cols], convert, store hi/lo ----
        {
#pragma unroll
            for (int q = 0; q < 2; q++) {
                int j = tid + q * 256;            // 512 float4 jobs
                int k_r = j >> 5;                 // 0..15
                int n4  = (j & 31) * 4;
                float4 v = *(const float4*)(W + (size_t)(kc * KC + k_r) * HC + colbase + n4);
                uint32_t h0,l0,h1,l1,h2,l2,h3,l3;
                split_tf32(v.x, h0, l0); split_tf32(v.y, h1, l1);
                split_tf32(v.z, h2, l2); split_tf32(v.w, h3, l3);
                Bs_hi[k_r][n4+0]=h0; Bs_hi[k_r][n4+1]=h1; Bs_hi[k_r][n4+2]=h2; Bs_hi[k_r][n4+3]=h3;
                Bs_lo[k_r][n4+0]=l0; Bs_lo[k_r][n4+1]=l1; Bs_lo[k_r][n4+2]=l2; Bs_lo[k_r][n4+3]=l3;
            }
        }
        __syncthreads();

        // ---- compute: 2 k-steps of 8 ----
#pragma unroll
        for (int ks = 0; ks < KC / 8; ks++) {
            int k0 = ks * 8;
            uint32_t a_hi[4][4], a_lo[4][4], b_hi[4][2], b_lo[4][2];
            int c0 = k0 + lc;
#pragma unroll
            for (int mt = 0; mt < 4; mt++) {
                int r = wm * 64 + mt * 16 + lr;
                a_hi[mt][0] = As_hi[c0  ][r];   a_hi[mt][1] = As_hi[c0  ][r+8];
                a_hi[mt][2] = As_hi[c0+4][r];   a_hi[mt][3] = As_hi[c0+4][r+8];
                a_lo[mt][0] = As_lo[c0  ][r];   a_lo[mt][1] = As_lo[c0  ][r+8];
                a_lo[mt][2] = As_lo[c0+4][r];   a_lo[mt][3] = As_lo[c0+4][r+8];
            }
#pragma unroll
            for (int nt = 0; nt < 4; nt++) {
                int n = wn * 32 + nt * 8 + lr;
                b_hi[nt][0] = Bs_hi[c0  ][n];   b_hi[nt][1] = Bs_hi[c0+4][n];
                b_lo[nt][0] = Bs_lo[c0  ][n];   b_lo[nt][1] = Bs_lo[c0+4][n];
            }
#pragma unroll
            for (int mt = 0; mt < 4; mt++)
#pragma unroll
                for (int nt = 0; nt < 4; nt++) {
                    mma_tf32(acc[mt][nt], a_hi[mt], b_hi[nt]);
                    mma_tf32(acc[mt][nt], a_hi[mt], b_lo[nt]);
                    mma_tf32(acc[mt][nt], a_lo[mt], b_hi[nt]);
                }
        }
    }

    // ---- epilogue: write fragments to C ----
#pragma unroll
    for (int mt = 0; mt < 4; mt++) {
        int r_lo = row0 + wm * 64 + mt * 16 + lr;
        int r_hi = r_lo + 8;
#pragma unroll
        for (int nt = 0; nt < 4; nt++) {
            int col = colbase + wn * 32 + nt * 8 + lc * 2;
            if (r_lo < M)
                *(float2*)(C + (size_t)r_lo * HC + col) =
                    make_float2(acc[mt][nt][0], acc[mt][nt][1]);
            if (r_hi < M)
                *(float2*)(C + (size_t)r_hi * HC + col) =
                    make_float2(acc[mt][nt][2], acc[mt][nt][3]);
        }
    }
}

// ---------------------------------------------------------------------------
// CSR build
// ---------------------------------------------------------------------------
__global__ void init_kernel(int n) {
    int i = blockIdx.x * blockDim.x + threadIdx.x;
    if (i < n) { g_deg[i] = 0; g_cur[i] = 0; }
}

__global__ void count_kernel(const int* __restrict__ dst, int E) {
    int i = blockIdx.x * blockDim.x + threadIdx.x;
    if (i < E) atomicAdd(&g_deg[dst[i]], 1);
}

// Phase 1: per-block inclusive scan of deg (1024/block), emit block sums.
__global__ void __launch_bounds__(1024) scan1_kernel(int n) {
    __shared__ int s[1024];
    int idx = blockIdx.x * 1024 + threadIdx.x;
    int v = (idx < n) ? g_deg[idx] : 0;
    s[threadIdx.x] = v;
    __syncthreads();
#pragma unroll
    for (int off = 1; off < 1024; off <<= 1) {
        int t = (threadIdx.x >= off) ? s[threadIdx.x - off] : 0;
        __syncthreads();
        s[threadIdx.x] += t;
        __syncthreads();
    }
    if (idx < n) g_scan[idx] = s[threadIdx.x];
    if (threadIdx.x == 1023) g_bsum[blockIdx.x] = s[1023];
}

// Phase 2: exclusive scan of block sums (nb <= 64), shared-memory Hillis-Steele.
__global__ void __launch_bounds__(64) scan2_kernel(int nb) {
    __shared__ int s[64];
    int t = threadIdx.x;
    int v0 = (t < nb) ? g_bsum[t] : 0;
    s[t] = v0;
    __syncthreads();
#pragma unroll
    for (int off = 1; off < 64; off <<= 1) {
        int u = (t >= off) ? s[t - off] : 0;
        __syncthreads();
        s[t] += u;
        __syncthreads();
    }
    if (t < nb) g_bpre[t] = s[t] - v0;    // inclusive -> exclusive
}

// Phase 3: add block prefixes, write exclusive offsets.
__global__ void scan3_kernel(int n) {
    int idx = blockIdx.x * 1024 + threadIdx.x;
    if (idx < n) g_offs[idx + 1] = g_scan[idx] + g_bpre[blockIdx.x];
    if (idx == 0) g_offs[0] = 0;
}

__global__ void scatter_kernel(const int* __restrict__ src,
                               const int* __restrict__ dst, int E) {
    int i = blockIdx.x * blockDim.x + threadIdx.x;
    if (i < E) {
        int d = dst[i];
        int pos = g_offs[d] + atomicAdd(&g_cur[d], 1);
        g_esrc[pos] = src[i];
    }
}

// ---------------------------------------------------------------------------
// Single-pass GATv2 aggregation.
// 4 nodes per 256-thread block; 64 threads per node (head = t64>>4, lane
// owns 4 channels via float4). Width-16 shuffle reduction per head.
// Online softmax without max-shift (|e| ~ N(0,~1), fp32-safe):
//   acc += exp(e)*XL[src], den += exp(e); out = mean_h(acc/den) + bias
// ---------------------------------------------------------------------------
__global__ void __launch_bounds__(256) agg_kernel(
    const float* __restrict__ att,
    const float* __restrict__ bias,
    float* __restrict__ out, int N)
{
    int tid = threadIdx.x;
    int nl   = tid >> 6;                  // node within block (0..3)
    int t64  = tid & 63;
    int node = blockIdx.x * 4 + nl;
    int head = t64 >> 4;
    int l16  = t64 & 15;
    int cbase = head * 64 + l16 * 4;

    __shared__ float s[4][4][64];         // [node][head][channel]

    if (node < N) {
        float4 xr4 = *(const float4*)(g_XR + (size_t)node * HC + cbase);
        float4 at4 = *(const float4*)(att + cbase);

        float4 acc = make_float4(0.f, 0.f, 0.f, 0.f);
        float den = 0.f;
        int beg = g_offs[node], end = g_offs[node + 1];

        for (int e = beg; e <= end; e++) {
            int src = (e < end) ? g_esrc[e] : node;   // e==end -> self loop
            float4 xl4 = *(const float4*)(g_XL + (size_t)src * HC + cbase);
            float m0 = xl4.x + xr4.x, m1 = xl4.y + xr4.y;
            float m2 = xl4.z + xr4.z, m3 = xl4.w + xr4.w;
            m0 = (m0 > 0.f) ? m0 : 0.2f * m0;
            m1 = (m1 > 0.f) ? m1 : 0.2f * m1;
            m2 = (m2 > 0.f) ? m2 : 0.2f * m2;
            m3 = (m3 > 0.f) ? m3 : 0.2f * m3;
            float d = m0 * at4.x + m1 * at4.y + m2 * at4.z + m3 * at4.w;
#pragma unroll
            for (int off = 8; off; off >>= 1)
                d += __shfl_xor_sync(0xffffffffu, d, off);
            float w = __expf(d);
            acc.x += w * xl4.x; acc.y += w * xl4.y;
            acc.z += w * xl4.z; acc.w += w * xl4.w;
            den += w;
        }

        float inv = 1.f / den;
        s[nl][head][l16 * 4 + 0] = acc.x * inv;
        s[nl][head][l16 * 4 + 1] = acc.y * inv;
        s[nl][head][l16 * 4 + 2] = acc.z * inv;
        s[nl][head][l16 * 4 + 3] = acc.w * inv;
    }
    __syncthreads();

    int c = tid & 63;
    if (node < N) {
        float v = 0.25f * (s[nl][0][c] + s[nl][1][c] + s[nl][2][c] + s[nl][3][c])
                + bias[c];
        out[(size_t)node * 64 + c] = v;
    }
}

// ---------------------------------------------------------------------------
extern "C" void kernel_launch(void* const* d_in, const int* in_sizes, int n_in,
                              void* d_out, int out_size)
{
    const float* x    = (const float*)d_in[0];
    const int*   ei   = (const int*)d_in[1];
    const float* Wl   = (const float*)d_in[2];
    const float* Wr   = (const float*)d_in[3];
    const float* att  = (const float*)d_in[4];
    const float* bias = (const float*)d_in[5];
    float*       out  = (float*)d_out;

    int N = in_sizes[0] / D_IN;
    int E = in_sizes[1] / 2;
    const int* src = ei;
    const int* dst = ei + E;

    init_kernel<<<(N + 255) / 256, 256>>>(N);

    dim3 ggrid((N + BM - 1) / BM, 4);
    gemm_kernel<<<ggrid, 256>>>(x, Wl, Wr, N);

    count_kernel<<<(E + 255) / 256, 256>>>(dst, E);

    int nb = (N + 1023) / 1024;
    scan1_kernel<<<nb, 1024>>>(N);
    scan2_kernel<<<1, 64>>>(nb);
    scan3_kernel<<<nb, 1024>>>(N);

    scatter_kernel<<<(E + 255) / 256, 256>>>(src, dst, E);

    agg_kernel<<<(N + 3) / 4, 256>>>(att, bias, out, N);
}